// round 3
// baseline (speedup 1.0000x reference)
#include <cuda_runtime.h>
#include <cuda_bf16.h>

#define NJ   24
#define FEAT 6
#define HID  7

typedef unsigned long long ull;

static __device__ __forceinline__ constexpr int PARENT(int j) {
    constexpr int P[NJ] = {-1,0,0,0,1,2,3,4,5,6,7,8,9,9,9,12,13,14,16,17,18,19,20,21};
    return P[j];
}

// f32x2 packed helpers
__device__ __forceinline__ ull pk(float lo, float hi) {
    ull r; asm("mov.b64 %0, {%1, %2};" : "=l"(r) : "f"(lo), "f"(hi)); return r;
}
__device__ __forceinline__ void upk(ull v, float& lo, float& hi) {
    asm("mov.b64 {%0, %1}, %2;" : "=f"(lo), "=f"(hi) : "l"(v));
}
__device__ __forceinline__ ull fma2(ull a, ull b, ull c) {
    ull d; asm("fma.rn.f32x2 %0, %1, %2, %3;" : "=l"(d) : "l"(a), "l"(b), "l"(c)); return d;
}

__device__ __forceinline__ float comp(const float4& v, int c) {
    return c == 0 ? v.x : (c == 1 ? v.y : (c == 2 ? v.z : v.w));
}

// Shared layout in PAIR units (float2 = one replicated weight {w,w}):
//  W1 : j*64 + r*8 + c     [0, 1536)
//  b1 : 1536 + j*8 + r     [1536, 1728)
//  W2 : 1728 + j*48 + q*8+c[1728, 2880)
//  b2 : 2880 + j*8 + q     [2880, 3072)
#define SP_B1 1536
#define SP_W2 1728
#define SP_B2 2880
#define SP_N  3072

__global__ __launch_bounds__(128, 2)
void se1d_kernel(const float* __restrict__ x,
                 const float* __restrict__ gW1, const float* __restrict__ gb1,
                 const float* __restrict__ gW2, const float* __restrict__ gb2,
                 float* __restrict__ out, int B, int Q4)
{
    __shared__ float2 sp[SP_N];
    const int tid = threadIdx.x;

    for (int i = tid; i < SP_N; i += 128) sp[i] = make_float2(0.f, 0.f);
    __syncthreads();
    for (int i = tid; i < NJ * 49; i += 128) {
        int j = i / 49, rem = i % 49, r = rem / 7, c = rem % 7;
        float w = gW1[i]; sp[j * 64 + r * 8 + c] = make_float2(w, w);
    }
    for (int i = tid; i < NJ * 7; i += 128) {
        int j = i / 7, r = i % 7;
        float w = gb1[i]; sp[SP_B1 + j * 8 + r] = make_float2(w, w);
    }
    for (int i = tid; i < NJ * 42; i += 128) {
        int j = i / 42, rem = i % 42, q = rem / 7, c = rem % 7;
        float w = gW2[i]; sp[SP_W2 + j * 48 + q * 8 + c] = make_float2(w, w);
    }
    for (int i = tid; i < NJ * 6; i += 128) {
        int j = i / 6, q = i % 6;
        float w = gb2[i]; sp[SP_B2 + j * 8 + q] = make_float2(w, w);
    }
    __syncthreads();

    const int g = blockIdx.x * 128 + tid;
    if (g >= Q4) return;

    // 4 sample streams, each internally coalesced across the warp.
    const long s0 = g;
    const long s1 = (long)g + Q4;
    const long s2 = (long)g + 2L * Q4;
    const long s3 = (long)g + 3L * Q4;
    const bool a1 = s1 < B, a2 = s2 < B, a3 = s3 < B;
    const long r1 = a1 ? s1 : (long)(B - 1);
    const long r2 = a2 ? s2 : (long)(B - 1);
    const long r3 = a3 ? s3 : (long)(B - 1);

    const float4* xv0 = (const float4*)(x + s0 * NJ);
    const float4* xv1 = (const float4*)(x + r1 * NJ);
    const float4* xv2 = (const float4*)(x + r2 * NJ);
    const float4* xv3 = (const float4*)(x + r3 * NJ);
    float* o0 = out + s0 * (NJ * FEAT);
    float* o1 = out + s1 * (NJ * FEAT);
    float* o2 = out + s2 * (NJ * FEAT);
    float* o3 = out + s3 * (NJ * FEAT);

    ull featp[NJ][FEAT][2];   // [joint][feat][pairA/pairB], compile-time indexed
    float4 x0c, x1c, x2c, x3c;

    #pragma unroll
    for (int j = 0; j < NJ; j++) {
        if ((j & 3) == 0) {
            const int k = j >> 2;
            x0c = __ldcs(xv0 + k); x1c = __ldcs(xv1 + k);
            x2c = __ldcs(xv2 + k); x3c = __ldcs(xv3 + k);
        }
        const int cc = j & 3;
        const ull xpA = pk(comp(x0c, cc), comp(x1c, cc));
        const ull xpB = pk(comp(x2c, cc), comp(x3c, cc));

        // ---- Layer 1: h = relu(W1 @ [x, parent_feat] + b1)
        const ulonglong2* bqp = (const ulonglong2*)&sp[SP_B1 + j * 8];
        const ulonglong2 bq0 = bqp[0], bq1 = bqp[1], bq2 = bqp[2], bq3 = bqp[3];

        ull hA[HID], hB[HID];
        #pragma unroll
        for (int r = 0; r < HID; r++) {
            const ulonglong2* wr = (const ulonglong2*)&sp[j * 64 + r * 8];
            const ulonglong2 k0 = wr[0], k1 = wr[1], k2 = wr[2], k3 = wr[3];
            const ull bias = (r == 0) ? bq0.x : (r == 1) ? bq0.y : (r == 2) ? bq1.x :
                             (r == 3) ? bq1.y : (r == 4) ? bq2.x : (r == 5) ? bq2.y : bq3.x;
            ull aA = fma2(k0.x, xpA, bias);
            ull aB = fma2(k0.x, xpB, bias);
            if (j > 0) {
                const int p = PARENT(j);
                aA = fma2(k0.y, featp[p][0][0], aA); aB = fma2(k0.y, featp[p][0][1], aB);
                aA = fma2(k1.x, featp[p][1][0], aA); aB = fma2(k1.x, featp[p][1][1], aB);
                aA = fma2(k1.y, featp[p][2][0], aA); aB = fma2(k1.y, featp[p][2][1], aB);
                aA = fma2(k2.x, featp[p][3][0], aA); aB = fma2(k2.x, featp[p][3][1], aB);
                aA = fma2(k2.y, featp[p][4][0], aA); aB = fma2(k2.y, featp[p][4][1], aB);
                aA = fma2(k3.x, featp[p][5][0], aA); aB = fma2(k3.x, featp[p][5][1], aB);
            }
            float l0, l1, l2, l3;
            upk(aA, l0, l1); upk(aB, l2, l3);
            hA[r] = pk(fmaxf(l0, 0.f), fmaxf(l1, 0.f));
            hB[r] = pk(fmaxf(l2, 0.f), fmaxf(l3, 0.f));
        }

        // ---- Layer 2: f = relu(W2 @ h + b2)
        const ulonglong2* cqp = (const ulonglong2*)&sp[SP_B2 + j * 8];
        const ulonglong2 cq0 = cqp[0], cq1 = cqp[1], cq2 = cqp[2];

        float f0[FEAT], f1[FEAT], f2[FEAT], f3[FEAT];
        #pragma unroll
        for (int q = 0; q < FEAT; q++) {
            const ulonglong2* wr = (const ulonglong2*)&sp[SP_W2 + j * 48 + q * 8];
            const ulonglong2 k0 = wr[0], k1 = wr[1], k2 = wr[2], k3 = wr[3];
            const ull bias = (q == 0) ? cq0.x : (q == 1) ? cq0.y : (q == 2) ? cq1.x :
                             (q == 3) ? cq1.y : (q == 4) ? cq2.x : cq2.y;
            ull aA = fma2(k0.x, hA[0], bias);
            ull aB = fma2(k0.x, hB[0], bias);
            aA = fma2(k0.y, hA[1], aA); aB = fma2(k0.y, hB[1], aB);
            aA = fma2(k1.x, hA[2], aA); aB = fma2(k1.x, hB[2], aB);
            aA = fma2(k1.y, hA[3], aA); aB = fma2(k1.y, hB[3], aB);
            aA = fma2(k2.x, hA[4], aA); aB = fma2(k2.x, hB[4], aB);
            aA = fma2(k2.y, hA[5], aA); aB = fma2(k2.y, hB[5], aB);
            aA = fma2(k3.x, hA[6], aA); aB = fma2(k3.x, hB[6], aB);
            float l0, l1, l2, l3;
            upk(aA, l0, l1); upk(aB, l2, l3);
            f0[q] = fmaxf(l0, 0.f); f1[q] = fmaxf(l1, 0.f);
            f2[q] = fmaxf(l2, 0.f); f3[q] = fmaxf(l3, 0.f);
            // Repack for children; dead entries (leaves) are DCE'd.
            featp[j][q][0] = pk(f0[q], f1[q]);
            featp[j][q][1] = pk(f2[q], f3[q]);
        }

        // ---- Stream outputs (float2, 8B-aligned: j*24B offset)
        float2* p0 = (float2*)(o0 + j * FEAT);
        __stcs(p0 + 0, make_float2(f0[0], f0[1]));
        __stcs(p0 + 1, make_float2(f0[2], f0[3]));
        __stcs(p0 + 2, make_float2(f0[4], f0[5]));
        if (a1) {
            float2* p1 = (float2*)(o1 + j * FEAT);
            __stcs(p1 + 0, make_float2(f1[0], f1[1]));
            __stcs(p1 + 1, make_float2(f1[2], f1[3]));
            __stcs(p1 + 2, make_float2(f1[4], f1[5]));
        }
        if (a2) {
            float2* p2 = (float2*)(o2 + j * FEAT);
            __stcs(p2 + 0, make_float2(f2[0], f2[1]));
            __stcs(p2 + 1, make_float2(f2[2], f2[3]));
            __stcs(p2 + 2, make_float2(f2[4], f2[5]));
        }
        if (a3) {
            float2* p3 = (float2*)(o3 + j * FEAT);
            __stcs(p3 + 0, make_float2(f3[0], f3[1]));
            __stcs(p3 + 1, make_float2(f3[2], f3[3]));
            __stcs(p3 + 2, make_float2(f3[4], f3[5]));
        }
    }
}

extern "C" void kernel_launch(void* const* d_in, const int* in_sizes, int n_in,
                              void* d_out, int out_size)
{
    const float* x  = (const float*)d_in[0];
    const float* W1 = (const float*)d_in[1];
    const float* b1 = (const float*)d_in[2];
    const float* W2 = (const float*)d_in[3];
    const float* b2 = (const float*)d_in[4];
    float* out = (float*)d_out;

    const int B  = in_sizes[0] / NJ;
    const int Q4 = (B + 3) / 4;
    const int grid = (Q4 + 127) / 128;
    se1d_kernel<<<grid, 128>>>(x, W1, b1, W2, b2, out, B, Q4);
}

// round 6
// speedup vs baseline: 2.3484x; 2.3484x over previous
#include <cuda_runtime.h>
#include <cuda_bf16.h>

#define NJ   24
#define FEAT 6
#define HID  7

// Identity order is topological: PARENTS[j] < j for all j>0.
static __device__ __forceinline__ constexpr int PARENT(int j) {
    constexpr int P[NJ] = {-1,0,0,0,1,2,3,4,5,6,7,8,9,9,9,12,13,14,16,17,18,19,20,21};
    return P[j];
}

__device__ __forceinline__ float comp(const float4& v, int c) {
    return c == 0 ? v.x : (c == 1 ? v.y : (c == 2 ? v.z : v.w));
}

// Padded shared-memory layout (rows padded to 8 floats for LDS.128):
//  W1: j*56 + r*8 + c          (1344 floats)   offset 0
//  b1: 1344 + j*8 + r          ( 192 floats)
//  W2: 1536 + j*48 + q*8 + c   (1152 floats)
//  b2: 2688 + j*8 + q          ( 192 floats)
#define SMEM_FLOATS 2880

__global__ __launch_bounds__(256, 2)
void se1d_kernel(const float* __restrict__ x,
                 const float* __restrict__ gW1, const float* __restrict__ gb1,
                 const float* __restrict__ gW2, const float* __restrict__ gb2,
                 float* __restrict__ out, int B, int Qh)
{
    __shared__ float s[SMEM_FLOATS];
    const int tid = threadIdx.x;

    for (int i = tid; i < SMEM_FLOATS; i += 256) s[i] = 0.f;
    __syncthreads();
    for (int i = tid; i < NJ * 49; i += 256) {
        int j = i / 49, rem = i % 49, r = rem / 7, c = rem % 7;
        s[j * 56 + r * 8 + c] = gW1[i];
    }
    for (int i = tid; i < NJ * 7; i += 256) {
        int j = i / 7, r = i % 7;
        s[1344 + j * 8 + r] = gb1[i];
    }
    for (int i = tid; i < NJ * 42; i += 256) {
        int j = i / 42, rem = i % 42, q = rem / 7, c = rem % 7;
        s[1536 + j * 48 + q * 8 + c] = gW2[i];
    }
    for (int i = tid; i < NJ * 6; i += 256) {
        int j = i / 6, q = i % 6;
        s[2688 + j * 8 + q] = gb2[i];
    }
    __syncthreads();

    const int g = blockIdx.x * 256 + tid;
    if (g >= Qh) return;

    // Two sample streams, each internally coalesced across the warp.
    const long s0 = g;
    const long s1 = (long)g + Qh;
    const bool a1 = s1 < B;
    const long r1 = a1 ? s1 : (long)(B - 1);

    const float4* xv0 = (const float4*)(x + s0 * NJ);
    const float4* xv1 = (const float4*)(x + r1 * NJ);
    float* o0 = out + s0 * (NJ * FEAT);
    float* o1 = out + s1 * (NJ * FEAT);

    // Compile-time indexed only -> registers; liveness prunes dead joints.
    float f0[NJ][FEAT], f1[NJ][FEAT];
    float4 xc0, xc1;
    const float4* s4 = (const float4*)s;

    #pragma unroll
    for (int j = 0; j < NJ; j++) {
        if ((j & 3) == 0) {
            xc0 = __ldcs(xv0 + (j >> 2));
            xc1 = __ldcs(xv1 + (j >> 2));
        }
        const int cc = j & 3;

        float in0[HID], in1[HID];
        in0[0] = comp(xc0, cc);
        in1[0] = comp(xc1, cc);
        if (j == 0) {
            #pragma unroll
            for (int f = 0; f < FEAT; f++) { in0[1 + f] = 0.f; in1[1 + f] = 0.f; }
        } else {
            const int p = PARENT(j);
            #pragma unroll
            for (int f = 0; f < FEAT; f++) { in0[1 + f] = f0[p][f]; in1[1 + f] = f1[p][f]; }
        }

        // ---- Layer 1: h = relu(W1 @ inp + b1), shared weight loads feed both samples
        float4 bb0 = s4[(1344 + j * 8) / 4];
        float4 bb1 = s4[(1344 + j * 8) / 4 + 1];
        const float bv[8] = {bb0.x, bb0.y, bb0.z, bb0.w, bb1.x, bb1.y, bb1.z, bb1.w};
        float h0[HID], h1[HID];
        #pragma unroll
        for (int r = 0; r < HID; r++) {
            float4 w0 = s4[(j * 56 + r * 8) / 4];
            float4 w1 = s4[(j * 56 + r * 8) / 4 + 1];
            float a0 = bv[r], a1v = bv[r];
            a0 = fmaf(w0.x, in0[0], a0);  a1v = fmaf(w0.x, in1[0], a1v);
            a0 = fmaf(w0.y, in0[1], a0);  a1v = fmaf(w0.y, in1[1], a1v);
            a0 = fmaf(w0.z, in0[2], a0);  a1v = fmaf(w0.z, in1[2], a1v);
            a0 = fmaf(w0.w, in0[3], a0);  a1v = fmaf(w0.w, in1[3], a1v);
            a0 = fmaf(w1.x, in0[4], a0);  a1v = fmaf(w1.x, in1[4], a1v);
            a0 = fmaf(w1.y, in0[5], a0);  a1v = fmaf(w1.y, in1[5], a1v);
            a0 = fmaf(w1.z, in0[6], a0);  a1v = fmaf(w1.z, in1[6], a1v);
            h0[r] = fmaxf(a0, 0.f);
            h1[r] = fmaxf(a1v, 0.f);
        }

        // ---- Layer 2: f = relu(W2 @ h + b2)
        float4 cb0 = s4[(2688 + j * 8) / 4];
        float4 cb1 = s4[(2688 + j * 8) / 4 + 1];
        const float cv[8] = {cb0.x, cb0.y, cb0.z, cb0.w, cb1.x, cb1.y, cb1.z, cb1.w};
        #pragma unroll
        for (int q = 0; q < FEAT; q++) {
            float4 w0 = s4[(1536 + j * 48 + q * 8) / 4];
            float4 w1 = s4[(1536 + j * 48 + q * 8) / 4 + 1];
            float a0 = cv[q], a1v = cv[q];
            a0 = fmaf(w0.x, h0[0], a0);  a1v = fmaf(w0.x, h1[0], a1v);
            a0 = fmaf(w0.y, h0[1], a0);  a1v = fmaf(w0.y, h1[1], a1v);
            a0 = fmaf(w0.z, h0[2], a0);  a1v = fmaf(w0.z, h1[2], a1v);
            a0 = fmaf(w0.w, h0[3], a0);  a1v = fmaf(w0.w, h1[3], a1v);
            a0 = fmaf(w1.x, h0[4], a0);  a1v = fmaf(w1.x, h1[4], a1v);
            a0 = fmaf(w1.y, h0[5], a0);  a1v = fmaf(w1.y, h1[5], a1v);
            a0 = fmaf(w1.z, h0[6], a0);  a1v = fmaf(w1.z, h1[6], a1v);
            f0[j][q] = fmaxf(a0, 0.f);
            f1[j][q] = fmaxf(a1v, 0.f);
        }

        // ---- Paired-joint streaming stores: joints (j-1, j) -> 3x STG.128 per sample.
        // (j-1)*6 floats offset = (j-1)*24 bytes; j-1 even -> 48B multiple -> 16B aligned.
        if (j & 1) {
            float4 v0 = make_float4(f0[j-1][0], f0[j-1][1], f0[j-1][2], f0[j-1][3]);
            float4 v1 = make_float4(f0[j-1][4], f0[j-1][5], f0[j][0],   f0[j][1]);
            float4 v2 = make_float4(f0[j][2],   f0[j][3],   f0[j][4],   f0[j][5]);
            float4* p0 = (float4*)(o0 + (j - 1) * FEAT);
            __stcs(p0 + 0, v0); __stcs(p0 + 1, v1); __stcs(p0 + 2, v2);
            if (a1) {
                float4 u0 = make_float4(f1[j-1][0], f1[j-1][1], f1[j-1][2], f1[j-1][3]);
                float4 u1 = make_float4(f1[j-1][4], f1[j-1][5], f1[j][0],   f1[j][1]);
                float4 u2 = make_float4(f1[j][2],   f1[j][3],   f1[j][4],   f1[j][5]);
                float4* p1 = (float4*)(o1 + (j - 1) * FEAT);
                __stcs(p1 + 0, u0); __stcs(p1 + 1, u1); __stcs(p1 + 2, u2);
            }
        }
    }
}

extern "C" void kernel_launch(void* const* d_in, const int* in_sizes, int n_in,
                              void* d_out, int out_size)
{
    const float* x  = (const float*)d_in[0];
    const float* W1 = (const float*)d_in[1];
    const float* b1 = (const float*)d_in[2];
    const float* W2 = (const float*)d_in[3];
    const float* b2 = (const float*)d_in[4];
    float* out = (float*)d_out;

    const int B  = in_sizes[0] / NJ;
    const int Qh = (B + 1) / 2;
    const int grid = (Qh + 255) / 256;
    se1d_kernel<<<grid, 256>>>(x, W1, b1, W2, b2, out, B, Qh);
}